// round 10
// baseline (speedup 1.0000x reference)
#include <cuda_runtime.h>
#include <cuda_fp16.h>
#include <cstdint>

#define XN 32
#define CIN 256
#define HIN 56
#define WIN 56
#define S_IN 3136
#define COUT 256
#define HOUT 28
#define WOUT 28
#define S_OUT 784
#define M_TOTAL 25088
#define X_ELEMS (XN * CIN * S_IN)

// Device scratch (no cudaMalloc allowed)
__device__ __align__(16) __half       g_xh[(size_t)XN * S_IN * CIN];   // 51.4 MB NHWC fp16
__device__ __align__(16) signed char  g_x8[(size_t)XN * S_IN * CIN];   // 25.7 MB NHWC s8
__device__ __align__(16) __half       g_wh[(size_t)COUT * 9 * CIN];    // [co][tap][ci] fp16
__device__ __align__(16) signed char  g_w8[(size_t)COUT * 9 * CIN];    // [co][tap][ci] s8

// ---------------------------------------------------------------------------
// Kernel 1: quantize x -> fp16 NHWC + s8 NHWC (two-phase smem reuse, R9-proven)
// ---------------------------------------------------------------------------
__global__ void quant_x_kernel(const float* __restrict__ x) {
    __shared__ __align__(16) unsigned char tbuf[32 * 260];
    __half*      th = (__half*)tbuf;        // pitch 130 halves (conflict-free)
    signed char* t8 = (signed char*)tbuf;   // pitch 132 bytes  (conflict-free)
    const int n  = blockIdx.z;
    const int c0 = blockIdx.y * 128;
    const int s0 = blockIdx.x * 32;
    const int t  = threadIdx.x;

    uint32_t qp[4] = {0, 0, 0, 0};
    const float* xb = x + (size_t)n * CIN * S_IN;
#pragma unroll
    for (int it = 0; it < 16; ++it) {
        int i  = it * 256 + t;
        int cl = i >> 5;
        int sl = i & 31;
        float v = xb[(size_t)(c0 + cl) * S_IN + (s0 + sl)];
        int q = __float2int_rn(v * 20.0f);   // round-half-even == jnp.round
        q = max(-128, min(127, q));
        th[sl * 130 + cl] = __int2half_rn(q);          // exact (|q|<=128)
        qp[it >> 2] |= ((uint32_t)(q & 0xff)) << (8 * (it & 3));
    }
    __syncthreads();

    __half* ob = g_xh + ((size_t)n * S_IN + s0) * CIN + c0;
#pragma unroll
    for (int it = 0; it < 8; ++it) {
        int u  = it * 256 + t;
        int sl = u >> 6;
        int cu = u & 63;
        uint32_t val = *(const uint32_t*)&th[sl * 130 + cu * 2];
        *(uint32_t*)&ob[(size_t)sl * CIN + cu * 2] = val;
    }
    __syncthreads();

#pragma unroll
    for (int it = 0; it < 16; ++it) {
        int i  = it * 256 + t;
        int cl = i >> 5;
        int sl = i & 31;
        t8[sl * 132 + cl] = (signed char)((qp[it >> 2] >> (8 * (it & 3))) & 0xff);
    }
    __syncthreads();

    signed char* ob8 = g_x8 + ((size_t)n * S_IN + s0) * CIN + c0;
#pragma unroll
    for (int it = 0; it < 4; ++it) {
        int j  = it * 256 + t;
        int sl = j >> 5;
        int c4 = j & 31;
        uint32_t val = *(const uint32_t*)&t8[sl * 132 + c4 * 4];
        *(uint32_t*)&ob8[(size_t)sl * CIN + c4 * 4] = val;
    }
}

// ---------------------------------------------------------------------------
// Kernel 2: weights OIHW fp32 (int-valued) -> [co][tap][ci] fp16 + s8
// ---------------------------------------------------------------------------
__global__ void quant_w_kernel(const float* __restrict__ w) {
    int idx = blockIdx.x * blockDim.x + threadIdx.x;
    if (idx >= COUT * 9 * CIN) return;
    int co  = idx / (9 * CIN);
    int r   = idx - co * 9 * CIN;
    int tap = r >> 8;
    int ci  = r & 255;
    int q = __float2int_rn(w[(size_t)co * CIN * 9 + (size_t)ci * 9 + tap]);
    g_wh[idx] = __int2half_rn(q);
    g_w8[idx] = (signed char)q;
}

// ---------------------------------------------------------------------------
// Kernel 3: same-warp dual-pipe conv. 512 threads, occ 1, warp grid 4x4,
// warp tile 32x32. Each of 12 outer iterations: 2 fp16 chunks (HMMA, tensor
// pipe) + 1 s8 chunk (emulated mma.s8 -> dp4a, fma pipe), all from the SAME
// warps so both pipes get issue slots from every warp. Both accumulator sets
// in registers; merged exactly at the epilogue (all integers < 2^24).
// ---------------------------------------------------------------------------
#define PITCH  144
#define TILEH  (128 * PITCH)           // 18432 (one fp16 tile)
#define HSTG   (2 * TILEH)             // A+B for one fp16 chunk
#define HBUFSZ (2 * HSTG)              // 2 chunks per iter buffer = 73728
#define PITCH8 80
#define TILE8  (128 * PITCH8)          // 10240
#define S8STG  (2 * TILE8)             // 20480
#define S8BASE (2 * HBUFSZ)            // 147456
#define SMEMT  (S8BASE + 2 * S8STG)    // 188416

__device__ __forceinline__ void cp16(uint32_t dst, const void* src, int sz) {
    asm volatile("cp.async.ca.shared.global [%0], [%1], 16, %2;\n"
                 :: "r"(dst), "l"(src), "r"(sz));
}
#define LDSM4(r0, r1, r2, r3, addr)                                          \
    asm volatile("ldmatrix.sync.aligned.m8n8.x4.shared.b16 {%0,%1,%2,%3}, [%4];" \
                 : "=r"(r0), "=r"(r1), "=r"(r2), "=r"(r3) : "r"(addr))
#define MMAF16(d, a, b0_, b1_)                                                \
    asm volatile(                                                             \
        "mma.sync.aligned.m16n8k16.row.col.f32.f16.f16.f32 "                 \
        "{%0,%1,%2,%3}, {%4,%5,%6,%7}, {%8,%9}, {%0,%1,%2,%3};\n"            \
        : "+f"(d[0]), "+f"(d[1]), "+f"(d[2]), "+f"(d[3])                     \
        : "r"(a[0]), "r"(a[1]), "r"(a[2]), "r"(a[3]), "r"(b0_), "r"(b1_))
#define MMAS8(d, a, b0_, b1_)                                                 \
    asm volatile(                                                             \
        "mma.sync.aligned.m16n8k32.row.col.s32.s8.s8.s32 "                   \
        "{%0,%1,%2,%3}, {%4,%5,%6,%7}, {%8,%9}, {%0,%1,%2,%3};\n"            \
        : "+r"(d[0]), "+r"(d[1]), "+r"(d[2]), "+r"(d[3])                     \
        : "r"(a[0]), "r"(a[1]), "r"(a[2]), "r"(a[3]), "r"(b0_), "r"(b1_))

__global__ void __launch_bounds__(512, 1) conv_dual_kernel(float* __restrict__ out) {
    extern __shared__ char dsm[];
    const uint32_t sbase = (uint32_t)__cvta_generic_to_shared(dsm);
    const int t      = threadIdx.x;
    const int lane   = t & 31;
    const int wid    = t >> 5;
    const int warp_m = wid & 3;        // 0..3
    const int warp_n = wid >> 2;       // 0..3
    const int m0     = blockIdx.x * 128;
    const int co0    = blockIdx.y * 128;

    // Loader mapping (512 thr): row = t/4 (0..127), base segment = t%4
    const int lrow = t >> 2;
    const int ls   = t & 3;

    int m   = m0 + lrow;
    int n   = m / S_OUT;
    int rem = m - n * S_OUT;
    int ho  = rem / WOUT;
    int wo  = rem - ho * WOUT;
    const int hb = 2 * ho - 1;
    const int wb = 2 * wo - 1;
    const __half*      anH = g_xh + (size_t)n * S_IN * CIN;
    const __half*      bwH = g_wh + (size_t)(co0 + lrow) * 9 * CIN;
    const signed char* an8 = g_x8 + (size_t)n * S_IN * CIN;
    const signed char* bw8 = g_w8 + (size_t)(co0 + lrow) * 9 * CIN;

    // ldmatrix lane offsets (proven fragment maps)
    const uint32_t a_lane  = (uint32_t)((lane & 15) * PITCH + (lane >> 4) * 16);
    const uint32_t b_lane  = (uint32_t)(((lane & 7) + ((lane >> 4) << 3)) * PITCH +
                                        (((lane >> 3) & 1) << 4));
    const uint32_t a_lane8 = (uint32_t)((lane & 15) * PITCH8 + (lane >> 4) * 16);
    const uint32_t b_lane8 = (uint32_t)(((lane & 7) + ((lane >> 4) << 3)) * PITCH8 +
                                        (((lane >> 3) & 1) << 4));

    float accH[2][4][4];
    int   acc8[2][4][4];
#pragma unroll
    for (int mi = 0; mi < 2; ++mi)
#pragma unroll
        for (int ni = 0; ni < 4; ++ni)
#pragma unroll
            for (int k = 0; k < 4; ++k) { accH[mi][ni][k] = 0.0f; acc8[mi][ni][k] = 0; }

    // issue loads for one fp16 chunk into (buf, slot j)
    auto issueH = [&](int c, int buf, int j) {
        int tap = c >> 2, kc = (c & 3) * 64;
        int kh = tap / 3, kw = tap - kh * 3;
        int hi = hb + kh, wi = wb + kw;
        bool v = ((unsigned)hi < (unsigned)HIN) && ((unsigned)wi < (unsigned)WIN);
        const __half* asrc = anH + ((size_t)(hi * WIN + wi) * CIN + kc);
        const __half* bsrc = bwH + (tap * CIN + kc);
        uint32_t base = sbase + (uint32_t)(buf * HBUFSZ + j * HSTG + lrow * PITCH);
#pragma unroll
        for (int jj = 0; jj < 2; ++jj) {
            int seg = ls + jj * 4;
            cp16(base + seg * 16,
                 v ? (const void*)(asrc + seg * 8) : (const void*)g_xh, v ? 16 : 0);
            cp16(base + TILEH + seg * 16, bsrc + seg * 8, 16);
        }
    };
    // issue loads for one s8 chunk into buf
    auto issue8 = [&](int c, int buf) {
        int tap = c >> 2, kc = (c & 3) * 64;
        int kh = tap / 3, kw = tap - kh * 3;
        int hi = hb + kh, wi = wb + kw;
        bool v = ((unsigned)hi < (unsigned)HIN) && ((unsigned)wi < (unsigned)WIN);
        const signed char* asrc = an8 + ((size_t)(hi * WIN + wi) * CIN + kc);
        const signed char* bsrc = bw8 + (tap * CIN + kc);
        uint32_t base = sbase + (uint32_t)(S8BASE + buf * S8STG + lrow * PITCH8);
        cp16(base + ls * 16,
             v ? (const void*)(asrc + ls * 16) : (const void*)g_x8, v ? 16 : 0);
        cp16(base + TILE8 + ls * 16, bsrc + ls * 16, 16);
    };
    auto issue_iter = [&](int i) {
        int buf = i & 1;
        issueH(3 * i, buf, 0);
        issueH(3 * i + 1, buf, 1);
        issue8(3 * i + 2, buf);
        asm volatile("cp.async.commit_group;\n" ::: "memory");
    };

    issue_iter(0);

#pragma unroll 1
    for (int i = 0; i < 12; ++i) {
        if (i < 11) {
            issue_iter(i + 1);
            asm volatile("cp.async.wait_group 1;\n" ::: "memory");
        } else {
            asm volatile("cp.async.wait_group 0;\n" ::: "memory");
        }
        __syncthreads();

        const int buf = i & 1;
        // ---- 2 fp16 chunks (tensor pipe) ----
#pragma unroll
        for (int j = 0; j < 2; ++j) {
            const uint32_t aB = sbase + (uint32_t)(buf * HBUFSZ + j * HSTG) +
                                (warp_m * 32) * PITCH + a_lane;
            const uint32_t bB = sbase + (uint32_t)(buf * HBUFSZ + j * HSTG + TILEH) +
                                (warp_n * 32) * PITCH + b_lane;
#pragma unroll
            for (int ks = 0; ks < 4; ++ks) {
                const uint32_t kb = ks * 32;
                uint32_t a[2][4];
                LDSM4(a[0][0], a[0][1], a[0][2], a[0][3], aB + kb);
                LDSM4(a[1][0], a[1][1], a[1][2], a[1][3], aB + 16 * PITCH + kb);
#pragma unroll
                for (int p = 0; p < 2; ++p) {
                    uint32_t b0, b1, b2, b3;
                    LDSM4(b0, b1, b2, b3, bB + p * (16 * PITCH) + kb);
#pragma unroll
                    for (int mi = 0; mi < 2; ++mi) {
                        MMAF16(accH[mi][2 * p],     a[mi], b0, b1);
                        MMAF16(accH[mi][2 * p + 1], a[mi], b2, b3);
                    }
                }
            }
        }
        // ---- 1 s8 chunk (fma pipe, dp4a emulation) ----
        {
            const uint32_t aB = sbase + (uint32_t)(S8BASE + buf * S8STG) +
                                (warp_m * 32) * PITCH8 + a_lane8;
            const uint32_t bB = sbase + (uint32_t)(S8BASE + buf * S8STG + TILE8) +
                                (warp_n * 32) * PITCH8 + b_lane8;
#pragma unroll
            for (int k2 = 0; k2 < 2; ++k2) {
                const uint32_t kb = k2 * 32;
                uint32_t a[2][4];
                LDSM4(a[0][0], a[0][1], a[0][2], a[0][3], aB + kb);
                LDSM4(a[1][0], a[1][1], a[1][2], a[1][3], aB + 16 * PITCH8 + kb);
#pragma unroll
                for (int p = 0; p < 2; ++p) {
                    uint32_t b0, b1, b2, b3;
                    LDSM4(b0, b1, b2, b3, bB + p * (16 * PITCH8) + kb);
#pragma unroll
                    for (int mi = 0; mi < 2; ++mi) {
                        MMAS8(acc8[mi][2 * p],     a[mi], b0, b1);
                        MMAS8(acc8[mi][2 * p + 1], a[mi], b2, b3);
                    }
                }
            }
        }
        __syncthreads();
    }

    // Epilogue: exact integer merge + dequantize, NCHW fp32 stores.
    const float sc = (float)(0.05 * 0.01);
#pragma unroll
    for (int mi = 0; mi < 2; ++mi) {
#pragma unroll
        for (int rr = 0; rr < 2; ++rr) {
            int mm = m0 + warp_m * 32 + mi * 16 + (lane >> 2) + rr * 8;
            int nn = mm / S_OUT;
            int ss = mm - nn * S_OUT;
            float* op = out + (size_t)nn * COUT * S_OUT + ss;
#pragma unroll
            for (int ni = 0; ni < 4; ++ni) {
                int co = co0 + warp_n * 32 + ni * 8 + (lane & 3) * 2;
                float v0 = accH[mi][ni][rr * 2 + 0] + (float)acc8[mi][ni][rr * 2 + 0];
                float v1 = accH[mi][ni][rr * 2 + 1] + (float)acc8[mi][ni][rr * 2 + 1];
                op[(size_t)co * S_OUT]       = v0 * sc;
                op[(size_t)(co + 1) * S_OUT] = v1 * sc;
            }
        }
    }
}

// ---------------------------------------------------------------------------
extern "C" void kernel_launch(void* const* d_in, const int* in_sizes, int n_in,
                              void* d_out, int out_size) {
    const float* x = (const float*)d_in[0];
    const float* w = (const float*)d_in[1];
    if (n_in >= 2 && in_sizes[0] != X_ELEMS) {
        const float* tmp = x; x = w; w = tmp;
    }
    float* out = (float*)d_out;

    dim3 g1(S_IN / 32, CIN / 128, XN);  // (98, 2, 32)
    quant_x_kernel<<<g1, 256>>>(x);

    quant_w_kernel<<<(COUT * 9 * CIN + 255) / 256, 256>>>(w);

    cudaFuncSetAttribute(conv_dual_kernel,
                         cudaFuncAttributeMaxDynamicSharedMemorySize, SMEMT);
    dim3 g3(M_TOTAL / 128, COUT / 128);  // (196, 2)
    conv_dual_kernel<<<g3, 512, SMEMT>>>(out);
}